// round 12
// baseline (speedup 1.0000x reference)
#include <cuda_runtime.h>
#include <math.h>
#include <stddef.h>
#include <stdint.h>

#define B_ 256
#define W_ 512
#define F_ 512
#define N_ 512
#define WT 16                 // words per tile (== #warps)
#define NT (W_ / WT)          // 32 tiles
#define NBUF 3                // pipeline depth (2 tiles in flight during compute)

// Scratch (device globals — no allocation allowed)
__device__ float g_t [B_*F_];   // t  = sum_w w[w]*x[b,w,:]
__device__ float g_q [B_*N_];   // Q  = t @ wq
__device__ float g_qk[B_*F_];   // qk = (Q @ wk^T) * rsqrt(N)
__device__ float g_y [B_*F_];   // y  = sum_w softmax_w * x[b,w,:]

// ---------------------------------------------------------------------------
// cp.async helpers
// ---------------------------------------------------------------------------
__device__ __forceinline__ void cp_async16(void* dst_smem, const void* src_gmem) {
    uint32_t d = (uint32_t)__cvta_generic_to_shared(dst_smem);
    asm volatile("cp.async.cg.shared.global [%0], [%1], 16;\n" :: "r"(d), "l"(src_gmem));
}
__device__ __forceinline__ void cp_commit() {
    asm volatile("cp.async.commit_group;\n");
}
template <int Nw>
__device__ __forceinline__ void cp_wait() {
    asm volatile("cp.async.wait_group %0;\n" :: "n"(Nw));
}

// Issue one WT x F_ tile (2048 float4) into smem buffer; 4 cp.async/thread.
__device__ __forceinline__ void issue_tile(float* dst, const float4* xb4,
                                           int t0, int tid) {
    #pragma unroll
    for (int j = 0; j < 4; j++) {
        int e = tid + j * 512;               // 0..2047
        int w = e >> 7, f4 = e & 127;
        cp_async16(&dst[w * F_ + f4 * 4], &xb4[(size_t)(t0 + w) * 128 + f4]);
    }
    cp_commit();
}

// ---------------------------------------------------------------------------
// Pass A: t[b][f] = sum_w w[w] * x[b][w][f]
// One CTA per batch, 512 threads, 2 CTAs/SM, 3-buffer cp.async pipeline with
// issue-before-wait schedule (R8-proven ordering, deeper prefetch).
// Tiles DESCENDING so pass B's start (w=0) is L2-warm.
// Dynamic smem: ws[512] | buf[3][WT*512]   (100352 B)
// ---------------------------------------------------------------------------
__global__ __launch_bounds__(512, 2) void k_t(const float* __restrict__ x,
                                              const float* __restrict__ wvec) {
    extern __shared__ float sm[];
    float* ws = sm;                          // 512
    float* bufs[NBUF] = { sm + F_, sm + F_ + WT * F_, sm + F_ + 2 * WT * F_ };

    const int b = blockIdx.x, tid = threadIdx.x;
    const float4* xb4 = (const float4*)(x + (size_t)b * W_ * F_);

    ws[tid] = wvec[tid];
    issue_tile(bufs[0], xb4, (NT - 1) * WT, tid);   // preload tiles NT-1, NT-2
    issue_tile(bufs[1], xb4, (NT - 2) * WT, tid);
    __syncthreads();                                // ws visible

    float acc = 0.f;
    for (int i = 0; i < NT; i++) {
        const int t = NT - 1 - i;            // descending
        const int cur = i % NBUF;
        if (i + 2 < NT) {
            issue_tile(bufs[(i + 2) % NBUF], xb4, (t - 2) * WT, tid);
            cp_wait<2>();                    // tile cur complete, 2 in flight
        } else {
            cp_wait<0>();
        }
        __syncthreads();                     // tile cur ready for all

        const float* xt  = bufs[cur];
        const float* wst = ws + t * WT;
        #pragma unroll
        for (int w = 0; w < WT; w++)
            acc += wst[w] * xt[w * F_ + tid];
        __syncthreads();                     // done reading cur before re-issue
    }
    g_t[b * F_ + tid] = acc;
}

// ---------------------------------------------------------------------------
// 32x32 tiled SGEMM, BK=32, 256 threads, 2x2 micro with LDS.64. (R8-proven)
// C = A[M,Kk] @ (TRANS_B ? Bm[Nn,Kk]^T : Bm[Kk,Nn]) * scale
// ---------------------------------------------------------------------------
template <int TRANS_B>
__global__ __launch_bounds__(256) void gemm32(const float* __restrict__ A,
                                              const float* __restrict__ Bm,
                                              float* __restrict__ C,
                                              int M, int Nn, int Kk, float scale) {
    __shared__ float As[32][36];
    __shared__ float Bs[32][36];
    const int tid = threadIdx.x;
    const int tx = tid & 15, ty = tid >> 4;
    const int m0 = blockIdx.y * 32, n0 = blockIdx.x * 32;
    float c00 = 0.f, c01 = 0.f, c10 = 0.f, c11 = 0.f;

    const int lm = tid >> 3, lk4 = tid & 7;

    for (int k0 = 0; k0 < Kk; k0 += 32) {
        {
            float4 v = *(const float4*)&A[(size_t)(m0 + lm) * Kk + k0 + lk4 * 4];
            As[lk4 * 4 + 0][lm] = v.x;
            As[lk4 * 4 + 1][lm] = v.y;
            As[lk4 * 4 + 2][lm] = v.z;
            As[lk4 * 4 + 3][lm] = v.w;
        }
        if (TRANS_B) {
            float4 v = *(const float4*)&Bm[(size_t)(n0 + lm) * Kk + k0 + lk4 * 4];
            Bs[lk4 * 4 + 0][lm] = v.x;
            Bs[lk4 * 4 + 1][lm] = v.y;
            Bs[lk4 * 4 + 2][lm] = v.z;
            Bs[lk4 * 4 + 3][lm] = v.w;
        } else {
            float4 v = *(const float4*)&Bm[(size_t)(k0 + lm) * Nn + n0 + lk4 * 4];
            Bs[lm][lk4 * 4 + 0] = v.x;
            Bs[lm][lk4 * 4 + 1] = v.y;
            Bs[lm][lk4 * 4 + 2] = v.z;
            Bs[lm][lk4 * 4 + 3] = v.w;
        }
        __syncthreads();
        #pragma unroll
        for (int k = 0; k < 32; k++) {
            const float2 a = *(const float2*)&As[k][ty * 2];
            const float2 b = *(const float2*)&Bs[k][tx * 2];
            c00 += a.x * b.x; c01 += a.x * b.y;
            c10 += a.y * b.x; c11 += a.y * b.y;
        }
        __syncthreads();
    }
    float* Cp = C + (size_t)(m0 + ty * 2) * Nn + n0 + tx * 2;
    Cp[0] = c00 * scale;  Cp[1] = c01 * scale;
    Cp[Nn] = c10 * scale; Cp[Nn + 1] = c11 * scale;
}

// ---------------------------------------------------------------------------
// Pass B: scores + online softmax + weighted accumulate. R8 compute skeleton,
// 3-buffer issue-before-wait pipeline, explicit tail barrier before re-issue.
// Dynamic smem: qks[512] | buf[3][WT*512]   (100352 B)
// ---------------------------------------------------------------------------
__global__ __launch_bounds__(512, 2) void k_attn(const float* __restrict__ x) {
    extern __shared__ float sm[];
    float* qks = sm;                   // 512
    float* bufs[NBUF] = { sm + F_, sm + F_ + WT * F_, sm + F_ + 2 * WT * F_ };
    __shared__ float sc[WT];
    __shared__ float ps[WT];

    const int b = blockIdx.x, tid = threadIdx.x;
    const int wi = tid >> 5, lane = tid & 31;

    qks[tid] = g_qk[b * F_ + tid];
    const float4* xb4 = (const float4*)(x + (size_t)b * W_ * F_);

    // Preload tiles 0,1
    issue_tile(bufs[0], xb4, 0, tid);
    issue_tile(bufs[1], xb4, WT, tid);
    __syncthreads();                         // qks visible

    float qkr[16];
    #pragma unroll
    for (int j = 0; j < 16; j++) qkr[j] = qks[lane + 32 * j];

    float m = -1e30f, s = 0.f, y = 0.f;

    for (int t = 0; t < NT; t++) {
        const int cur = t % NBUF;
        if (t + 2 < NT) {
            issue_tile(bufs[(t + 2) % NBUF], xb4, (t + 2) * WT, tid);
            cp_wait<2>();                    // tile cur complete, 2 in flight
        } else {
            cp_wait<0>();
        }
        __syncthreads();                     // tile cur ready for all

        // Each warp: one word's dot product (qk already carries rsqrt(N))
        float d = 0.f;
        const float* xw = &bufs[cur][wi * F_];
        #pragma unroll
        for (int j = 0; j < 16; j++) d += xw[lane + 32 * j] * qkr[j];
        #pragma unroll
        for (int o = 16; o > 0; o >>= 1) d += __shfl_xor_sync(0xffffffffu, d, o);
        if (lane == 0) sc[wi] = d;
        __syncthreads();                     // sc ready

        // mn/corr uniform across threads; p[w] computed once by 16 threads
        float mn = m;
        #pragma unroll
        for (int w = 0; w < WT; w++) mn = fmaxf(mn, sc[w]);
        const float corr = __expf(m - mn);
        if (tid < WT) ps[tid] = __expf(sc[tid] - mn);
        m = mn;
        __syncthreads();                     // ps ready

        // Accumulate (thread owns f = tid)
        float pr[WT];
        #pragma unroll
        for (int w = 0; w < WT; w++) pr[w] = ps[w];
        float psum = 0.f;
        #pragma unroll
        for (int w = 0; w < WT; w++) psum += pr[w];
        s = s * corr + psum;
        y *= corr;
        #pragma unroll
        for (int w = 0; w < WT; w++) y += pr[w] * bufs[cur][w * F_ + tid];
        __syncthreads();                     // all done reading cur before re-issue
    }
    g_y[b * F_ + tid] = y / s;
}

// ---------------------------------------------------------------------------
extern "C" void kernel_launch(void* const* d_in, const int* in_sizes, int n_in,
                              void* d_out, int out_size) {
    const float* x    = (const float*)d_in[0];
    const float* wk   = (const float*)d_in[1];
    const float* wq   = (const float*)d_in[2];
    const float* wv   = (const float*)d_in[3];
    const float* wvec = (const float*)d_in[4];
    float* out = (float*)d_out;

    float *pt, *pq, *pqk, *py;
    cudaGetSymbolAddress((void**)&pt,  g_t);
    cudaGetSymbolAddress((void**)&pq,  g_q);
    cudaGetSymbolAddress((void**)&pqk, g_qk);
    cudaGetSymbolAddress((void**)&py,  g_y);

    const int pipe_smem = (F_ + NBUF * WT * F_) * sizeof(float);   // 100352
    cudaFuncSetAttribute(k_t,    cudaFuncAttributeMaxDynamicSharedMemorySize, pipe_smem);
    cudaFuncSetAttribute(k_attn, cudaFuncAttributeMaxDynamicSharedMemorySize, pipe_smem);

    const float rsqrtN = 0.04419417382415922f;  // 1/sqrt(512)

    // Pass A over x: t
    k_t<<<B_, 512, pipe_smem>>>(x, wvec);
    // Q = t @ wq                 (256x512x512)
    gemm32<0><<<dim3(N_ / 32, B_ / 32), 256>>>(pt, wq, pq, B_, N_, F_, 1.f);
    // qk = (Q @ wk^T) * rsqrtN   (256x512x512)
    gemm32<1><<<dim3(F_ / 32, B_ / 32), 256>>>(pq, wk, pqk, B_, F_, N_, rsqrtN);
    // Pass B over x: attention
    k_attn<<<B_, 512, pipe_smem>>>(x);
    // out = y @ wv               (256x512x512)
    gemm32<0><<<dim3(N_ / 32, B_ / 32), 256>>>(py, wv, out, B_, N_, F_, 1.f);
}

// round 13
// speedup vs baseline: 1.1377x; 1.1377x over previous
#include <cuda_runtime.h>
#include <math.h>
#include <stddef.h>
#include <stdint.h>

#define B_ 256
#define W_ 512
#define F_ 512
#define N_ 512
#define WT 16                 // words per tile (== #warps)
#define NT (W_ / WT)          // 32 tiles
#define NBQK 128              // grid of the fused qk kernel (co-resident: <=1/SM)

// Scratch (device globals — no allocation allowed)
__device__ float g_t [B_*F_];   // t  = sum_w w[w]*x[b,w,:]
__device__ float g_q [B_*N_];   // Q  = t @ wq
__device__ float g_qk[B_*F_];   // qk = (Q @ wk^T) * rsqrt(N)
__device__ float g_y [B_*F_];   // y  = sum_w softmax_w * x[b,w,:]

// Grid barrier state for the fused qk kernel (monotonic across graph replays)
__device__ unsigned g_arrive = 0;
__device__ volatile unsigned g_release = 0;

__device__ __forceinline__ void grid_sync_128() {
    __syncthreads();
    if (threadIdx.x == 0) {
        __threadfence();                                  // publish this CTA's writes
        unsigned t = atomicAdd(&g_arrive, 1u) + 1u;       // 1-based ticket
        unsigned gen = (t - 1u) / NBQK + 1u;
        if (t == gen * NBQK) {
            g_release = gen;                              // last arriver releases
            __threadfence();
        } else {
            while (g_release < gen) { __nanosleep(64); }
            __threadfence();                              // acquire
        }
    }
    __syncthreads();
}

// ---------------------------------------------------------------------------
// cp.async helpers
// ---------------------------------------------------------------------------
__device__ __forceinline__ void cp_async16(void* dst_smem, const void* src_gmem) {
    uint32_t d = (uint32_t)__cvta_generic_to_shared(dst_smem);
    asm volatile("cp.async.cg.shared.global [%0], [%1], 16;\n" :: "r"(d), "l"(src_gmem));
}
__device__ __forceinline__ void cp_commit() {
    asm volatile("cp.async.commit_group;\n");
}
template <int Nw>
__device__ __forceinline__ void cp_wait() {
    asm volatile("cp.async.wait_group %0;\n" :: "n"(Nw));
}

// Issue one WT x F_ tile (2048 float4) into smem buffer; 4 cp.async/thread.
__device__ __forceinline__ void issue_tile(float* dst, const float4* xb4,
                                           int t0, int tid) {
    #pragma unroll
    for (int j = 0; j < 4; j++) {
        int e = tid + j * 512;               // 0..2047
        int w = e >> 7, f4 = e & 127;
        cp_async16(&dst[w * F_ + f4 * 4], &xb4[(size_t)(t0 + w) * 128 + f4]);
    }
    cp_commit();
}

// ---------------------------------------------------------------------------
// Pass A: t[b][f] = sum_w w[w] * x[b][w][f]
// One CTA per batch, 512 threads, 2 CTAs/SM, 2-buffer cp.async pipeline
// (R8-proven schedule). Tiles DESCENDING so pass B's start (w=0) is L2-warm.
// Tail barrier removed: re-issued cp.async data lands >=400cyc after issue,
// laggard readers of the same buffer are <=~100cyc behind (same argument that
// k_attn has validated since R6).
// Dynamic smem: ws[512] | buf0[WT*512] | buf1[WT*512]   (67584 B)
// ---------------------------------------------------------------------------
__global__ __launch_bounds__(512, 2) void k_t(const float* __restrict__ x,
                                              const float* __restrict__ wvec) {
    extern __shared__ float sm[];
    float* ws   = sm;                        // 512
    float* bufs[2] = { sm + F_, sm + F_ + WT * F_ };

    const int b = blockIdx.x, tid = threadIdx.x;
    const float4* xb4 = (const float4*)(x + (size_t)b * W_ * F_);

    ws[tid] = wvec[tid];
    issue_tile(bufs[0], xb4, (NT - 1) * WT, tid);   // preload last tile
    __syncthreads();                                // ws visible

    float acc = 0.f;
    for (int i = 0; i < NT; i++) {
        const int t = NT - 1 - i;            // descending
        const int cur = i & 1, nxt = cur ^ 1;
        if (i < NT - 1) {
            issue_tile(bufs[nxt], xb4, (t - 1) * WT, tid);
            cp_wait<1>();                    // current tile's group done
        } else {
            cp_wait<0>();
        }
        __syncthreads();                     // tile cur ready for all

        const float* xt  = bufs[cur];
        const float* wst = ws + t * WT;
        #pragma unroll
        for (int w = 0; w < WT; w++)
            acc += wst[w] * xt[w * F_ + tid];
        // no tail barrier (latency-cover; see header comment)
    }
    g_t[b * F_ + tid] = acc;
}

// ---------------------------------------------------------------------------
// 32x32 GEMM tile body, BK=32, 256 threads, 2x2 micro with LDS.64. (R8-proven)
// C[m0:+32][n0:+32] = A[m0:+32,:Kk] @ (TRANS_B ? Bm^T : Bm) * scale
// ---------------------------------------------------------------------------
template <int TRANS_B>
__device__ __forceinline__ void gemm32_body(const float* __restrict__ A,
                                            const float* __restrict__ Bm,
                                            float* __restrict__ C,
                                            int m0, int n0,
                                            int Nn, int Kk, float scale,
                                            float (*As)[36], float (*Bs)[36]) {
    const int tid = threadIdx.x;
    const int tx = tid & 15, ty = tid >> 4;
    float c00 = 0.f, c01 = 0.f, c10 = 0.f, c11 = 0.f;

    const int lm = tid >> 3, lk4 = tid & 7;

    for (int k0 = 0; k0 < Kk; k0 += 32) {
        {
            float4 v = *(const float4*)&A[(size_t)(m0 + lm) * Kk + k0 + lk4 * 4];
            As[lk4 * 4 + 0][lm] = v.x;
            As[lk4 * 4 + 1][lm] = v.y;
            As[lk4 * 4 + 2][lm] = v.z;
            As[lk4 * 4 + 3][lm] = v.w;
        }
        if (TRANS_B) {
            float4 v = *(const float4*)&Bm[(size_t)(n0 + lm) * Kk + k0 + lk4 * 4];
            Bs[lk4 * 4 + 0][lm] = v.x;
            Bs[lk4 * 4 + 1][lm] = v.y;
            Bs[lk4 * 4 + 2][lm] = v.z;
            Bs[lk4 * 4 + 3][lm] = v.w;
        } else {
            float4 v = *(const float4*)&Bm[(size_t)(k0 + lm) * Nn + n0 + lk4 * 4];
            Bs[lm][lk4 * 4 + 0] = v.x;
            Bs[lm][lk4 * 4 + 1] = v.y;
            Bs[lm][lk4 * 4 + 2] = v.z;
            Bs[lm][lk4 * 4 + 3] = v.w;
        }
        __syncthreads();
        #pragma unroll
        for (int k = 0; k < 32; k++) {
            const float2 a = *(const float2*)&As[k][ty * 2];
            const float2 b = *(const float2*)&Bs[k][tx * 2];
            c00 += a.x * b.x; c01 += a.x * b.y;
            c10 += a.y * b.x; c11 += a.y * b.y;
        }
        __syncthreads();
    }
    float* Cp = C + (size_t)(m0 + ty * 2) * Nn + n0 + tx * 2;
    Cp[0] = c00 * scale;  Cp[1] = c01 * scale;
    Cp[Nn] = c10 * scale; Cp[Nn + 1] = c11 * scale;
}

// Standalone gemm (for out = y @ wv)
template <int TRANS_B>
__global__ __launch_bounds__(256) void gemm32(const float* __restrict__ A,
                                              const float* __restrict__ Bm,
                                              float* __restrict__ C,
                                              int M, int Nn, int Kk, float scale) {
    __shared__ float As[32][36];
    __shared__ float Bs[32][36];
    gemm32_body<TRANS_B>(A, Bm, C, blockIdx.y * 32, blockIdx.x * 32,
                         Nn, Kk, scale, As, Bs);
}

// Fused Q = t@wq then qk = (Q@wk^T)*rsqrtN.  128 CTAs (one 32x32 tile per
// phase each), software grid barrier between phases. 128 <= 148 SMs and
// 9.2KB smem -> trivially co-resident, deadlock-free.
__global__ __launch_bounds__(256) void k_qk(const float* __restrict__ wq,
                                            const float* __restrict__ wk,
                                            float rsqrtN) {
    __shared__ float As[32][36];
    __shared__ float Bs[32][36];
    const int cta = blockIdx.x;              // 0..127 over 8x16 tiles
    const int m0 = (cta >> 4) * 32, n0 = (cta & 15) * 32;

    gemm32_body<0>(g_t, wq, g_q, m0, n0, N_, F_, 1.f, As, Bs);
    grid_sync_128();
    gemm32_body<1>(g_q, wk, g_qk, m0, n0, F_, N_, rsqrtN, As, Bs);
}

// ---------------------------------------------------------------------------
// Pass B: scores + online softmax + weighted accumulate. EXACT R8 structure
// (52.5us standalone, proven twice).
// Dynamic smem: qks[512] | buf0[WT*512] | buf1[WT*512]   (67584 B)
// ---------------------------------------------------------------------------
__global__ __launch_bounds__(512, 2) void k_attn(const float* __restrict__ x) {
    extern __shared__ float sm[];
    float* qks  = sm;                  // 512
    float* bufs[2] = { sm + F_, sm + F_ + WT * F_ };
    __shared__ float sc[WT];
    __shared__ float ps[WT];

    const int b = blockIdx.x, tid = threadIdx.x;
    const int wi = tid >> 5, lane = tid & 31;

    qks[tid] = g_qk[b * F_ + tid];
    const float4* xb4 = (const float4*)(x + (size_t)b * W_ * F_);

    // Preload tile 0
    issue_tile(bufs[0], xb4, 0, tid);
    __syncthreads();                         // qks visible

    float qkr[16];
    #pragma unroll
    for (int j = 0; j < 16; j++) qkr[j] = qks[lane + 32 * j];

    float m = -1e30f, s = 0.f, y = 0.f;

    for (int t = 0; t < NT; t++) {
        const int cur = t & 1, nxt = cur ^ 1;
        if (t < NT - 1) {
            issue_tile(bufs[nxt], xb4, (t + 1) * WT, tid);
            cp_wait<1>();
        } else {
            cp_wait<0>();
        }
        __syncthreads();                     // tile cur ready (also guards sc reuse)

        // Each warp: one word's dot product (qk already carries rsqrt(N))
        float d = 0.f;
        const float* xw = &bufs[cur][wi * F_];
        #pragma unroll
        for (int j = 0; j < 16; j++) d += xw[lane + 32 * j] * qkr[j];
        #pragma unroll
        for (int o = 16; o > 0; o >>= 1) d += __shfl_xor_sync(0xffffffffu, d, o);
        if (lane == 0) sc[wi] = d;
        __syncthreads();                     // sc ready

        // mn/corr uniform across threads; p[w] computed once by 16 threads
        float mn = m;
        #pragma unroll
        for (int w = 0; w < WT; w++) mn = fmaxf(mn, sc[w]);
        const float corr = __expf(m - mn);
        if (tid < WT) ps[tid] = __expf(sc[tid] - mn);
        m = mn;
        __syncthreads();                     // ps ready

        // Accumulate (thread owns f = tid)
        float pr[WT];
        #pragma unroll
        for (int w = 0; w < WT; w++) pr[w] = ps[w];
        float psum = 0.f;
        #pragma unroll
        for (int w = 0; w < WT; w++) psum += pr[w];
        s = s * corr + psum;
        y *= corr;
        #pragma unroll
        for (int w = 0; w < WT; w++) y += pr[w] * bufs[cur][w * F_ + tid];
        // no tail barrier: in-flight cp.async arrival latency covers the next
        // iteration's writes into the buffer being drained.
    }
    g_y[b * F_ + tid] = y / s;
}

// ---------------------------------------------------------------------------
extern "C" void kernel_launch(void* const* d_in, const int* in_sizes, int n_in,
                              void* d_out, int out_size) {
    const float* x    = (const float*)d_in[0];
    const float* wk   = (const float*)d_in[1];
    const float* wq   = (const float*)d_in[2];
    const float* wv   = (const float*)d_in[3];
    const float* wvec = (const float*)d_in[4];
    float* out = (float*)d_out;

    float* py;
    cudaGetSymbolAddress((void**)&py, g_y);

    const int pipe_smem = (F_ + 2 * WT * F_) * sizeof(float);   // 67584
    cudaFuncSetAttribute(k_t,    cudaFuncAttributeMaxDynamicSharedMemorySize, pipe_smem);
    cudaFuncSetAttribute(k_attn, cudaFuncAttributeMaxDynamicSharedMemorySize, pipe_smem);

    const float rsqrtN = 0.04419417382415922f;  // 1/sqrt(512)

    // Pass A over x: t
    k_t<<<B_, 512, pipe_smem>>>(x, wvec);
    // qk = (t @ wq @ wk^T) * rsqrtN   (fused, one launch, grid barrier inside)
    k_qk<<<NBQK, 256>>>(wq, wk, rsqrtN);
    // Pass B over x: attention
    k_attn<<<B_, 512, pipe_smem>>>(x);
    // out = y @ wv               (256x512x512)
    gemm32<0><<<dim3(N_ / 32, B_ / 32), 256>>>(py, wv, out, B_, N_, F_, 1.f);
}

// round 14
// speedup vs baseline: 1.2414x; 1.0912x over previous
#include <cuda_runtime.h>
#include <math.h>
#include <stddef.h>
#include <stdint.h>

#define B_ 256
#define W_ 512
#define F_ 512
#define N_ 512
#define WT 16                 // words per tile (== #warps)
#define NT (W_ / WT)          // 32 tiles
#define NBQK 128              // grid of the fused qk kernel (co-resident: <=1/SM)

// Scratch (device globals — no allocation allowed)
__device__ float g_t [B_*F_];   // t  = sum_w w[w]*x[b,w,:]
__device__ float g_q [B_*N_];   // Q  = t @ wq
__device__ float g_qk[B_*F_];   // qk = (Q @ wk^T) * rsqrt(N)
__device__ float g_y [B_*F_];   // y  = sum_w softmax_w * x[b,w,:]

// Grid barrier state for the fused qk kernel (monotonic across graph replays)
__device__ unsigned g_arrive = 0;
__device__ volatile unsigned g_release = 0;

__device__ __forceinline__ void grid_sync_128() {
    __syncthreads();
    if (threadIdx.x == 0) {
        __threadfence();                                  // publish this CTA's writes
        unsigned t = atomicAdd(&g_arrive, 1u) + 1u;       // 1-based ticket
        unsigned gen = (t - 1u) / NBQK + 1u;
        if (t == gen * NBQK) {
            g_release = gen;                              // last arriver releases
            __threadfence();
        } else {
            while (g_release < gen) { __nanosleep(64); }
            __threadfence();                              // acquire
        }
    }
    __syncthreads();
}

// ---------------------------------------------------------------------------
// cp.async helpers
// ---------------------------------------------------------------------------
__device__ __forceinline__ void cp_async16(void* dst_smem, const void* src_gmem) {
    uint32_t d = (uint32_t)__cvta_generic_to_shared(dst_smem);
    asm volatile("cp.async.cg.shared.global [%0], [%1], 16;\n" :: "r"(d), "l"(src_gmem));
}
__device__ __forceinline__ void cp_commit() {
    asm volatile("cp.async.commit_group;\n");
}
template <int Nw>
__device__ __forceinline__ void cp_wait() {
    asm volatile("cp.async.wait_group %0;\n" :: "n"(Nw));
}

// Issue one WT x F_ tile (2048 float4) into smem buffer; 4 cp.async/thread.
__device__ __forceinline__ void issue_tile(float* dst, const float4* xb4,
                                           int t0, int tid) {
    #pragma unroll
    for (int j = 0; j < 4; j++) {
        int e = tid + j * 512;               // 0..2047
        int w = e >> 7, f4 = e & 127;
        cp_async16(&dst[w * F_ + f4 * 4], &xb4[(size_t)(t0 + w) * 128 + f4]);
    }
    cp_commit();
}

// ---------------------------------------------------------------------------
// Pass A: t[b][f] = sum_w w[w] * x[b][w][f]
// One CTA per batch, 512 threads, 2 CTAs/SM, 2-buffer cp.async pipeline
// (R8-proven schedule). Tiles DESCENDING so pass B's start (w=0) is L2-warm.
// Dynamic smem: ws[512] | buf0[WT*512] | buf1[WT*512]   (67584 B)
// ---------------------------------------------------------------------------
__global__ __launch_bounds__(512, 2) void k_t(const float* __restrict__ x,
                                              const float* __restrict__ wvec) {
    extern __shared__ float sm[];
    float* ws   = sm;                        // 512
    float* bufs[2] = { sm + F_, sm + F_ + WT * F_ };

    const int b = blockIdx.x, tid = threadIdx.x;
    const float4* xb4 = (const float4*)(x + (size_t)b * W_ * F_);

    ws[tid] = wvec[tid];
    issue_tile(bufs[0], xb4, (NT - 1) * WT, tid);   // preload last tile
    __syncthreads();                                // ws visible

    float acc = 0.f;
    for (int i = 0; i < NT; i++) {
        const int t = NT - 1 - i;            // descending
        const int cur = i & 1, nxt = cur ^ 1;
        if (i < NT - 1) {
            issue_tile(bufs[nxt], xb4, (t - 1) * WT, tid);
            cp_wait<1>();                    // current tile's group done
        } else {
            cp_wait<0>();
        }
        __syncthreads();                     // tile cur ready for all

        const float* xt  = bufs[cur];
        const float* wst = ws + t * WT;
        #pragma unroll
        for (int w = 0; w < WT; w++)
            acc += wst[w] * xt[w * F_ + tid];
        // no tail barrier (latency-cover argument, validated since R6)
    }
    g_t[b * F_ + tid] = acc;
}

// ---------------------------------------------------------------------------
// 32x32 GEMM tile body, BK=32, 256 threads, 2x2 micro, LDS.64 compute reads,
// NOW with register prefetch: next k-block's LDGs issue right after the
// store barrier and overlap the 32-k compute, instead of stalling the store.
// C[m0:+32][n0:+32] = A[m0:+32,:Kk] @ (TRANS_B ? Bm^T : Bm) * scale
// ---------------------------------------------------------------------------
template <int TRANS_B>
__device__ __forceinline__ void gemm32_body(const float* __restrict__ A,
                                            const float* __restrict__ Bm,
                                            float* __restrict__ C,
                                            int m0, int n0,
                                            int Nn, int Kk, float scale,
                                            float (*As)[36], float (*Bs)[36]) {
    const int tid = threadIdx.x;
    const int tx = tid & 15, ty = tid >> 4;
    const int lm = tid >> 3, lk4 = tid & 7;
    float c00 = 0.f, c01 = 0.f, c10 = 0.f, c11 = 0.f;

    // Prologue loads (k0 = 0)
    float4 va = *(const float4*)&A[(size_t)(m0 + lm) * Kk + lk4 * 4];
    float4 vb;
    if (TRANS_B) vb = *(const float4*)&Bm[(size_t)(n0 + lm) * Kk + lk4 * 4];
    else         vb = *(const float4*)&Bm[(size_t)lm * Nn + n0 + lk4 * 4];

    for (int k0 = 0; k0 < Kk; k0 += 32) {
        __syncthreads();                     // smem free (prev compute/invocation done)
        As[lk4 * 4 + 0][lm] = va.x;
        As[lk4 * 4 + 1][lm] = va.y;
        As[lk4 * 4 + 2][lm] = va.z;
        As[lk4 * 4 + 3][lm] = va.w;
        if (TRANS_B) {
            Bs[lk4 * 4 + 0][lm] = vb.x;
            Bs[lk4 * 4 + 1][lm] = vb.y;
            Bs[lk4 * 4 + 2][lm] = vb.z;
            Bs[lk4 * 4 + 3][lm] = vb.w;
        } else {
            Bs[lm][lk4 * 4 + 0] = vb.x;
            Bs[lm][lk4 * 4 + 1] = vb.y;
            Bs[lm][lk4 * 4 + 2] = vb.z;
            Bs[lm][lk4 * 4 + 3] = vb.w;
        }
        __syncthreads();                     // tiles visible

        // Prefetch next k-block (latency overlaps the compute below)
        if (k0 + 32 < Kk) {
            va = *(const float4*)&A[(size_t)(m0 + lm) * Kk + k0 + 32 + lk4 * 4];
            if (TRANS_B) vb = *(const float4*)&Bm[(size_t)(n0 + lm) * Kk + k0 + 32 + lk4 * 4];
            else         vb = *(const float4*)&Bm[(size_t)(k0 + 32 + lm) * Nn + n0 + lk4 * 4];
        }

        #pragma unroll
        for (int k = 0; k < 32; k++) {
            const float2 a = *(const float2*)&As[k][ty * 2];
            const float2 b = *(const float2*)&Bs[k][tx * 2];
            c00 += a.x * b.x; c01 += a.x * b.y;
            c10 += a.y * b.x; c11 += a.y * b.y;
        }
    }
    float* Cp = C + (size_t)(m0 + ty * 2) * Nn + n0 + tx * 2;
    Cp[0] = c00 * scale;  Cp[1] = c01 * scale;
    Cp[Nn] = c10 * scale; Cp[Nn + 1] = c11 * scale;
}

// Standalone gemm (for out = y @ wv)
template <int TRANS_B>
__global__ __launch_bounds__(256) void gemm32(const float* __restrict__ A,
                                              const float* __restrict__ Bm,
                                              float* __restrict__ C,
                                              int M, int Nn, int Kk, float scale) {
    __shared__ float As[32][36];
    __shared__ float Bs[32][36];
    gemm32_body<TRANS_B>(A, Bm, C, blockIdx.y * 32, blockIdx.x * 32,
                         Nn, Kk, scale, As, Bs);
}

// Fused Q = t@wq then qk = (Q@wk^T)*rsqrtN.  128 CTAs, software grid barrier.
__global__ __launch_bounds__(256) void k_qk(const float* __restrict__ wq,
                                            const float* __restrict__ wk,
                                            float rsqrtN) {
    __shared__ float As[32][36];
    __shared__ float Bs[32][36];
    const int cta = blockIdx.x;              // 0..127 over 8x16 tiles
    const int m0 = (cta >> 4) * 32, n0 = (cta & 15) * 32;

    gemm32_body<0>(g_t, wq, g_q, m0, n0, N_, F_, 1.f, As, Bs);
    grid_sync_128();
    gemm32_body<1>(g_q, wk, g_qk, m0, n0, F_, N_, rsqrtN, As, Bs);
}

// ---------------------------------------------------------------------------
// Pass B: scores + online softmax + weighted accumulate. EXACT R8 structure.
// Dynamic smem: qks[512] | buf0[WT*512] | buf1[WT*512]   (67584 B)
// ---------------------------------------------------------------------------
__global__ __launch_bounds__(512, 2) void k_attn(const float* __restrict__ x) {
    extern __shared__ float sm[];
    float* qks  = sm;                  // 512
    float* bufs[2] = { sm + F_, sm + F_ + WT * F_ };
    __shared__ float sc[WT];
    __shared__ float ps[WT];

    const int b = blockIdx.x, tid = threadIdx.x;
    const int wi = tid >> 5, lane = tid & 31;

    qks[tid] = g_qk[b * F_ + tid];
    const float4* xb4 = (const float4*)(x + (size_t)b * W_ * F_);

    // Preload tile 0
    issue_tile(bufs[0], xb4, 0, tid);
    __syncthreads();                         // qks visible

    float qkr[16];
    #pragma unroll
    for (int j = 0; j < 16; j++) qkr[j] = qks[lane + 32 * j];

    float m = -1e30f, s = 0.f, y = 0.f;

    for (int t = 0; t < NT; t++) {
        const int cur = t & 1, nxt = cur ^ 1;
        if (t < NT - 1) {
            issue_tile(bufs[nxt], xb4, (t + 1) * WT, tid);
            cp_wait<1>();
        } else {
            cp_wait<0>();
        }
        __syncthreads();                     // tile cur ready (also guards sc reuse)

        // Each warp: one word's dot product (qk already carries rsqrt(N))
        float d = 0.f;
        const float* xw = &bufs[cur][wi * F_];
        #pragma unroll
        for (int j = 0; j < 16; j++) d += xw[lane + 32 * j] * qkr[j];
        #pragma unroll
        for (int o = 16; o > 0; o >>= 1) d += __shfl_xor_sync(0xffffffffu, d, o);
        if (lane == 0) sc[wi] = d;
        __syncthreads();                     // sc ready

        // mn/corr uniform across threads; p[w] computed once by 16 threads
        float mn = m;
        #pragma unroll
        for (int w = 0; w < WT; w++) mn = fmaxf(mn, sc[w]);
        const float corr = __expf(m - mn);
        if (tid < WT) ps[tid] = __expf(sc[tid] - mn);
        m = mn;
        __syncthreads();                     // ps ready

        // Accumulate (thread owns f = tid)
        float pr[WT];
        #pragma unroll
        for (int w = 0; w < WT; w++) pr[w] = ps[w];
        float psum = 0.f;
        #pragma unroll
        for (int w = 0; w < WT; w++) psum += pr[w];
        s = s * corr + psum;
        y *= corr;
        #pragma unroll
        for (int w = 0; w < WT; w++) y += pr[w] * bufs[cur][w * F_ + tid];
        // no tail barrier: cp.async arrival latency covers the next writes.
    }
    g_y[b * F_ + tid] = y / s;
}

// ---------------------------------------------------------------------------
extern "C" void kernel_launch(void* const* d_in, const int* in_sizes, int n_in,
                              void* d_out, int out_size) {
    const float* x    = (const float*)d_in[0];
    const float* wk   = (const float*)d_in[1];
    const float* wq   = (const float*)d_in[2];
    const float* wv   = (const float*)d_in[3];
    const float* wvec = (const float*)d_in[4];
    float* out = (float*)d_out;

    float* py;
    cudaGetSymbolAddress((void**)&py, g_y);

    const int pipe_smem = (F_ + 2 * WT * F_) * sizeof(float);   // 67584
    cudaFuncSetAttribute(k_t,    cudaFuncAttributeMaxDynamicSharedMemorySize, pipe_smem);
    cudaFuncSetAttribute(k_attn, cudaFuncAttributeMaxDynamicSharedMemorySize, pipe_smem);

    const float rsqrtN = 0.04419417382415922f;  // 1/sqrt(512)

    // Pass A over x: t
    k_t<<<B_, 512, pipe_smem>>>(x, wvec);
    // qk = (t @ wq @ wk^T) * rsqrtN   (fused, grid barrier inside)
    k_qk<<<NBQK, 256>>>(wq, wk, rsqrtN);
    // Pass B over x: attention
    k_attn<<<B_, 512, pipe_smem>>>(x);
    // out = y @ wv               (256x512x512)
    gemm32<0><<<dim3(N_ / 32, B_ / 32), 256>>>(py, wv, out, B_, N_, F_, 1.f);
}

// round 15
// speedup vs baseline: 1.3214x; 1.0644x over previous
#include <cuda_runtime.h>
#include <math.h>
#include <stddef.h>
#include <stdint.h>

#define B_ 256
#define W_ 512
#define F_ 512
#define N_ 512
#define WT 16                 // words per tile (== #warps)
#define NT (W_ / WT)          // 32 tiles
#define NBQK 128              // grid of the fused qk kernel (co-resident: <=1/SM)

// Scratch (device globals — no allocation allowed)
__device__ float g_t [B_*F_];   // t  = sum_w w[w]*x[b,w,:]
__device__ float g_q [B_*N_];   // Q  = t @ wq
__device__ float g_qk[B_*F_];   // qk = (Q @ wk^T) * rsqrt(N)
__device__ float g_y [B_*F_];   // y  = sum_w softmax_w * x[b,w,:]

// Grid barrier state for the fused qk kernel (monotonic across graph replays)
__device__ unsigned g_arrive = 0;
__device__ volatile unsigned g_release = 0;

__device__ __forceinline__ void grid_sync_128() {
    __syncthreads();
    if (threadIdx.x == 0) {
        __threadfence();                                  // publish this CTA's writes
        unsigned t = atomicAdd(&g_arrive, 1u) + 1u;       // 1-based ticket
        unsigned gen = (t - 1u) / NBQK + 1u;
        if (t == gen * NBQK) {
            g_release = gen;                              // last arriver releases
            __threadfence();
        } else {
            while (g_release < gen) { __nanosleep(64); }
            __threadfence();                              // acquire
        }
    }
    __syncthreads();
}

// ---------------------------------------------------------------------------
// cp.async helpers
// ---------------------------------------------------------------------------
__device__ __forceinline__ void cp_async16(void* dst_smem, const void* src_gmem) {
    uint32_t d = (uint32_t)__cvta_generic_to_shared(dst_smem);
    asm volatile("cp.async.cg.shared.global [%0], [%1], 16;\n" :: "r"(d), "l"(src_gmem));
}
__device__ __forceinline__ void cp_commit() {
    asm volatile("cp.async.commit_group;\n");
}
template <int Nw>
__device__ __forceinline__ void cp_wait() {
    asm volatile("cp.async.wait_group %0;\n" :: "n"(Nw));
}

// Issue one WT x F_ tile (2048 float4) into smem buffer; 4 cp.async/thread.
__device__ __forceinline__ void issue_tile(float* dst, const float4* xb4,
                                           int t0, int tid) {
    #pragma unroll
    for (int j = 0; j < 4; j++) {
        int e = tid + j * 512;               // 0..2047
        int w = e >> 7, f4 = e & 127;
        cp_async16(&dst[w * F_ + f4 * 4], &xb4[(size_t)(t0 + w) * 128 + f4]);
    }
    cp_commit();
}

// ---------------------------------------------------------------------------
// Pass A: t[b][f] = sum_w w[w] * x[b][w][f]
// One CTA per batch, 512 threads, 2 CTAs/SM, 2-buffer cp.async pipeline
// (R8-proven schedule). Tiles DESCENDING so pass B's start (w=0) is L2-warm.
// Dynamic smem: ws[512] | buf0[WT*512] | buf1[WT*512]   (67584 B)
// ---------------------------------------------------------------------------
__global__ __launch_bounds__(512, 2) void k_t(const float* __restrict__ x,
                                              const float* __restrict__ wvec) {
    extern __shared__ float sm[];
    float* ws   = sm;                        // 512
    float* bufs[2] = { sm + F_, sm + F_ + WT * F_ };

    const int b = blockIdx.x, tid = threadIdx.x;
    const float4* xb4 = (const float4*)(x + (size_t)b * W_ * F_);

    ws[tid] = wvec[tid];
    issue_tile(bufs[0], xb4, (NT - 1) * WT, tid);   // preload last tile
    __syncthreads();                                // ws visible

    float acc = 0.f;
    for (int i = 0; i < NT; i++) {
        const int t = NT - 1 - i;            // descending
        const int cur = i & 1, nxt = cur ^ 1;
        if (i < NT - 1) {
            issue_tile(bufs[nxt], xb4, (t - 1) * WT, tid);
            cp_wait<1>();                    // current tile's group done
        } else {
            cp_wait<0>();
        }
        __syncthreads();                     // tile cur ready for all

        const float* xt  = bufs[cur];
        const float* wst = ws + t * WT;
        #pragma unroll
        for (int w = 0; w < WT; w++)
            acc += wst[w] * xt[w * F_ + tid];
        // no tail barrier (latency-cover argument, validated since R6)
    }
    g_t[b * F_ + tid] = acc;
}

// ---------------------------------------------------------------------------
// Split-K x2 32x32 GEMM tile body, 512 threads (two 256-thread halves, each
// accumulating half of K into its own smem tile pair; lockstep barriers; smem
// reduction at the end). Register prefetch of the next k-block overlaps
// compute. C[m0:+32][n0:+32] = A[m0:+32,:Kk] @ (TRANS_B ? Bm^T : Bm) * scale
// ---------------------------------------------------------------------------
template <int TRANS_B>
__device__ __forceinline__ void gemm32k2_body(const float* __restrict__ A,
                                              const float* __restrict__ Bm,
                                              float* __restrict__ C,
                                              int m0, int n0,
                                              int Nn, int Kk, float scale,
                                              float (*As)[32][36],
                                              float (*Bs)[32][36],
                                              float (*Cred)[33]) {
    const int tid = threadIdx.x;
    const int half = tid >> 8;               // 0 or 1
    const int t = tid & 255;
    const int tx = t & 15, ty = t >> 4;
    const int lm = t >> 3, lk4 = t & 7;
    const int kbase = half * (Kk >> 1);
    const int nk = Kk >> 1;                  // K per half
    float c00 = 0.f, c01 = 0.f, c10 = 0.f, c11 = 0.f;

    // Prologue loads for this half's first k-block
    float4 va = *(const float4*)&A[(size_t)(m0 + lm) * Kk + kbase + lk4 * 4];
    float4 vb;
    if (TRANS_B) vb = *(const float4*)&Bm[(size_t)(n0 + lm) * Kk + kbase + lk4 * 4];
    else         vb = *(const float4*)&Bm[(size_t)(kbase + lm) * Nn + n0 + lk4 * 4];

    for (int k0 = 0; k0 < nk; k0 += 32) {    // both halves: same trip count
        __syncthreads();                     // smem free
        As[half][lk4 * 4 + 0][lm] = va.x;
        As[half][lk4 * 4 + 1][lm] = va.y;
        As[half][lk4 * 4 + 2][lm] = va.z;
        As[half][lk4 * 4 + 3][lm] = va.w;
        if (TRANS_B) {
            Bs[half][lk4 * 4 + 0][lm] = vb.x;
            Bs[half][lk4 * 4 + 1][lm] = vb.y;
            Bs[half][lk4 * 4 + 2][lm] = vb.z;
            Bs[half][lk4 * 4 + 3][lm] = vb.w;
        } else {
            Bs[half][lm][lk4 * 4 + 0] = vb.x;
            Bs[half][lm][lk4 * 4 + 1] = vb.y;
            Bs[half][lm][lk4 * 4 + 2] = vb.z;
            Bs[half][lm][lk4 * 4 + 3] = vb.w;
        }
        __syncthreads();                     // tiles visible

        // Prefetch next k-block (overlaps compute)
        if (k0 + 32 < nk) {
            const int kk = kbase + k0 + 32;
            va = *(const float4*)&A[(size_t)(m0 + lm) * Kk + kk + lk4 * 4];
            if (TRANS_B) vb = *(const float4*)&Bm[(size_t)(n0 + lm) * Kk + kk + lk4 * 4];
            else         vb = *(const float4*)&Bm[(size_t)(kk + lm) * Nn + n0 + lk4 * 4];
        }

        #pragma unroll
        for (int k = 0; k < 32; k++) {
            const float2 a = *(const float2*)&As[half][k][ty * 2];
            const float2 b = *(const float2*)&Bs[half][k][tx * 2];
            c00 += a.x * b.x; c01 += a.x * b.y;
            c10 += a.y * b.x; c11 += a.y * b.y;
        }
    }

    // Cross-half reduction via smem
    __syncthreads();                         // all compute done
    if (half == 1) {
        Cred[ty * 2    ][tx * 2    ] = c00;
        Cred[ty * 2    ][tx * 2 + 1] = c01;
        Cred[ty * 2 + 1][tx * 2    ] = c10;
        Cred[ty * 2 + 1][tx * 2 + 1] = c11;
    }
    __syncthreads();
    if (half == 0) {
        c00 += Cred[ty * 2    ][tx * 2    ];
        c01 += Cred[ty * 2    ][tx * 2 + 1];
        c10 += Cred[ty * 2 + 1][tx * 2    ];
        c11 += Cred[ty * 2 + 1][tx * 2 + 1];
        float* Cp = C + (size_t)(m0 + ty * 2) * Nn + n0 + tx * 2;
        Cp[0] = c00 * scale;  Cp[1] = c01 * scale;
        Cp[Nn] = c10 * scale; Cp[Nn + 1] = c11 * scale;
    }
    __syncthreads();                         // Cred reusable by caller's next call
}

// Standalone split-K gemm (for out = y @ wv)
template <int TRANS_B>
__global__ __launch_bounds__(512) void gemm32k2(const float* __restrict__ A,
                                                const float* __restrict__ Bm,
                                                float* __restrict__ C,
                                                int M, int Nn, int Kk, float scale) {
    __shared__ float As[2][32][36];
    __shared__ float Bs[2][32][36];
    __shared__ float Cred[32][33];
    gemm32k2_body<TRANS_B>(A, Bm, C, blockIdx.y * 32, blockIdx.x * 32,
                           Nn, Kk, scale, As, Bs, Cred);
}

// Fused Q = t@wq then qk = (Q@wk^T)*rsqrtN.  128 CTAs x 512 thr, grid barrier.
__global__ __launch_bounds__(512) void k_qk(const float* __restrict__ wq,
                                            const float* __restrict__ wk,
                                            float rsqrtN) {
    __shared__ float As[2][32][36];
    __shared__ float Bs[2][32][36];
    __shared__ float Cred[32][33];
    const int cta = blockIdx.x;              // 0..127 over 8x16 tiles
    const int m0 = (cta >> 4) * 32, n0 = (cta & 15) * 32;

    gemm32k2_body<0>(g_t, wq, g_q, m0, n0, N_, F_, 1.f, As, Bs, Cred);
    grid_sync_128();
    gemm32k2_body<1>(g_q, wk, g_qk, m0, n0, F_, N_, rsqrtN, As, Bs, Cred);
}

// ---------------------------------------------------------------------------
// Pass B: scores + online softmax + weighted accumulate. EXACT R8 structure.
// Dynamic smem: qks[512] | buf0[WT*512] | buf1[WT*512]   (67584 B)
// ---------------------------------------------------------------------------
__global__ __launch_bounds__(512, 2) void k_attn(const float* __restrict__ x) {
    extern __shared__ float sm[];
    float* qks  = sm;                  // 512
    float* bufs[2] = { sm + F_, sm + F_ + WT * F_ };
    __shared__ float sc[WT];
    __shared__ float ps[WT];

    const int b = blockIdx.x, tid = threadIdx.x;
    const int wi = tid >> 5, lane = tid & 31;

    qks[tid] = g_qk[b * F_ + tid];
    const float4* xb4 = (const float4*)(x + (size_t)b * W_ * F_);

    // Preload tile 0
    issue_tile(bufs[0], xb4, 0, tid);
    __syncthreads();                         // qks visible

    float qkr[16];
    #pragma unroll
    for (int j = 0; j < 16; j++) qkr[j] = qks[lane + 32 * j];

    float m = -1e30f, s = 0.f, y = 0.f;

    for (int t = 0; t < NT; t++) {
        const int cur = t & 1, nxt = cur ^ 1;
        if (t < NT - 1) {
            issue_tile(bufs[nxt], xb4, (t + 1) * WT, tid);
            cp_wait<1>();
        } else {
            cp_wait<0>();
        }
        __syncthreads();                     // tile cur ready (also guards sc reuse)

        // Each warp: one word's dot product (qk already carries rsqrt(N))
        float d = 0.f;
        const float* xw = &bufs[cur][wi * F_];
        #pragma unroll
        for (int j = 0; j < 16; j++) d += xw[lane + 32 * j] * qkr[j];
        #pragma unroll
        for (int o = 16; o > 0; o >>= 1) d += __shfl_xor_sync(0xffffffffu, d, o);
        if (lane == 0) sc[wi] = d;
        __syncthreads();                     // sc ready

        // mn/corr uniform across threads; p[w] computed once by 16 threads
        float mn = m;
        #pragma unroll
        for (int w = 0; w < WT; w++) mn = fmaxf(mn, sc[w]);
        const float corr = __expf(m - mn);
        if (tid < WT) ps[tid] = __expf(sc[tid] - mn);
        m = mn;
        __syncthreads();                     // ps ready

        // Accumulate (thread owns f = tid)
        float pr[WT];
        #pragma unroll
        for (int w = 0; w < WT; w++) pr[w] = ps[w];
        float psum = 0.f;
        #pragma unroll
        for (int w = 0; w < WT; w++) psum += pr[w];
        s = s * corr + psum;
        y *= corr;
        #pragma unroll
        for (int w = 0; w < WT; w++) y += pr[w] * bufs[cur][w * F_ + tid];
        // no tail barrier: cp.async arrival latency covers the next writes.
    }
    g_y[b * F_ + tid] = y / s;
}

// ---------------------------------------------------------------------------
extern "C" void kernel_launch(void* const* d_in, const int* in_sizes, int n_in,
                              void* d_out, int out_size) {
    const float* x    = (const float*)d_in[0];
    const float* wk   = (const float*)d_in[1];
    const float* wq   = (const float*)d_in[2];
    const float* wv   = (const float*)d_in[3];
    const float* wvec = (const float*)d_in[4];
    float* out = (float*)d_out;

    float* py;
    cudaGetSymbolAddress((void**)&py, g_y);

    const int pipe_smem = (F_ + 2 * WT * F_) * sizeof(float);   // 67584
    cudaFuncSetAttribute(k_t,    cudaFuncAttributeMaxDynamicSharedMemorySize, pipe_smem);
    cudaFuncSetAttribute(k_attn, cudaFuncAttributeMaxDynamicSharedMemorySize, pipe_smem);

    const float rsqrtN = 0.04419417382415922f;  // 1/sqrt(512)

    // Pass A over x: t
    k_t<<<B_, 512, pipe_smem>>>(x, wvec);
    // qk = (t @ wq @ wk^T) * rsqrtN   (fused, grid barrier inside)
    k_qk<<<NBQK, 512>>>(wq, wk, rsqrtN);
    // Pass B over x: attention
    k_attn<<<B_, 512, pipe_smem>>>(x);
    // out = y @ wv               (256x512x512, split-K x2)
    gemm32k2<0><<<dim3(N_ / 32, B_ / 32), 512>>>(py, wv, out, B_, N_, F_, 1.f);
}

// round 16
// speedup vs baseline: 1.3638x; 1.0321x over previous
#include <cuda_runtime.h>
#include <math.h>
#include <stddef.h>
#include <stdint.h>

#define B_ 256
#define W_ 512
#define F_ 512
#define N_ 512
#define WT 16                 // words per tile (== #warps)
#define NT (W_ / WT)          // 32 tiles
#define NBQK 128              // grid of the fused qk kernel (co-resident: <=1/SM)

// Scratch (device globals — no allocation allowed)
__device__ float g_t [B_*F_];   // t  = sum_w w[w]*x[b,w,:]
__device__ float g_q [B_*N_];   // Q  = t @ wq
__device__ float g_qk[B_*F_];   // qk = (Q @ wk^T) * rsqrt(N)
__device__ float g_y [B_*F_];   // y  = sum_w softmax_w * x[b,w,:]

// Grid barrier state for the fused qk kernel (monotonic across graph replays)
__device__ unsigned g_arrive = 0;
__device__ volatile unsigned g_release = 0;

__device__ __forceinline__ void grid_sync_128() {
    __syncthreads();
    if (threadIdx.x == 0) {
        __threadfence();                                  // publish this CTA's writes
        unsigned t = atomicAdd(&g_arrive, 1u) + 1u;       // 1-based ticket
        unsigned gen = (t - 1u) / NBQK + 1u;
        if (t == gen * NBQK) {
            g_release = gen;                              // last arriver releases
            __threadfence();
        } else {
            while (g_release < gen) { __nanosleep(64); }
            __threadfence();                              // acquire
        }
    }
    __syncthreads();
}

// ---------------------------------------------------------------------------
// cp.async helpers
// ---------------------------------------------------------------------------
__device__ __forceinline__ void cp_async16(void* dst_smem, const void* src_gmem) {
    uint32_t d = (uint32_t)__cvta_generic_to_shared(dst_smem);
    asm volatile("cp.async.cg.shared.global [%0], [%1], 16;\n" :: "r"(d), "l"(src_gmem));
}
__device__ __forceinline__ void cp_commit() {
    asm volatile("cp.async.commit_group;\n");
}
template <int Nw>
__device__ __forceinline__ void cp_wait() {
    asm volatile("cp.async.wait_group %0;\n" :: "n"(Nw));
}

// Issue one WT x F_ tile (2048 float4) into smem buffer; 4 cp.async/thread.
__device__ __forceinline__ void issue_tile(float* dst, const float4* xb4,
                                           int t0, int tid) {
    #pragma unroll
    for (int j = 0; j < 4; j++) {
        int e = tid + j * 512;               // 0..2047
        int w = e >> 7, f4 = e & 127;
        cp_async16(&dst[w * F_ + f4 * 4], &xb4[(size_t)(t0 + w) * 128 + f4]);
    }
    cp_commit();
}

// ---------------------------------------------------------------------------
// Pass A: t[b][f] = sum_w w[w] * x[b][w][f]
// One CTA per batch, 512 threads, 2 CTAs/SM, 2-buffer cp.async pipeline
// (R8-proven schedule). Tiles DESCENDING so pass B's start (w=0) is L2-warm.
// Dynamic smem: ws[512] | buf0[WT*512] | buf1[WT*512]   (67584 B)
// ---------------------------------------------------------------------------
__global__ __launch_bounds__(512, 2) void k_t(const float* __restrict__ x,
                                              const float* __restrict__ wvec) {
    extern __shared__ float sm[];
    float* ws   = sm;                        // 512
    float* bufs[2] = { sm + F_, sm + F_ + WT * F_ };

    const int b = blockIdx.x, tid = threadIdx.x;
    const float4* xb4 = (const float4*)(x + (size_t)b * W_ * F_);

    ws[tid] = wvec[tid];
    issue_tile(bufs[0], xb4, (NT - 1) * WT, tid);   // preload last tile
    __syncthreads();                                // ws visible

    float acc = 0.f;
    for (int i = 0; i < NT; i++) {
        const int t = NT - 1 - i;            // descending
        const int cur = i & 1, nxt = cur ^ 1;
        if (i < NT - 1) {
            issue_tile(bufs[nxt], xb4, (t - 1) * WT, tid);
            cp_wait<1>();                    // current tile's group done
        } else {
            cp_wait<0>();
        }
        __syncthreads();                     // tile cur ready for all

        const float* xt  = bufs[cur];
        const float* wst = ws + t * WT;
        #pragma unroll
        for (int w = 0; w < WT; w++)
            acc += wst[w] * xt[w * F_ + tid];
        // no tail barrier (latency-cover argument, validated since R6)
    }
    g_t[b * F_ + tid] = acc;
}

// ---------------------------------------------------------------------------
// Split-K x4 32x32 GEMM tile body, 1024 threads (four 256-thread quarters,
// each accumulating K/4 into its own smem tile pair; lockstep barriers;
// pairwise smem reduction at the end). Register prefetch overlaps compute.
// C[m0:+32][n0:+32] = A[m0:+32,:Kk] @ (TRANS_B ? Bm^T : Bm) * scale
// ---------------------------------------------------------------------------
template <int TRANS_B>
__device__ __forceinline__ void gemm32k4_body(const float* __restrict__ A,
                                              const float* __restrict__ Bm,
                                              float* __restrict__ C,
                                              int m0, int n0,
                                              int Nn, int Kk, float scale,
                                              float (*As)[32][36],
                                              float (*Bs)[32][36],
                                              float (*Cred)[32][33]) {
    const int tid = threadIdx.x;
    const int qr = tid >> 8;                 // quarter 0..3
    const int t = tid & 255;
    const int tx = t & 15, ty = t >> 4;
    const int lm = t >> 3, lk4 = t & 7;
    const int nk = Kk >> 2;                  // K per quarter (128)
    const int kbase = qr * nk;
    float c00 = 0.f, c01 = 0.f, c10 = 0.f, c11 = 0.f;

    // Prologue loads for this quarter's first k-block
    float4 va = *(const float4*)&A[(size_t)(m0 + lm) * Kk + kbase + lk4 * 4];
    float4 vb;
    if (TRANS_B) vb = *(const float4*)&Bm[(size_t)(n0 + lm) * Kk + kbase + lk4 * 4];
    else         vb = *(const float4*)&Bm[(size_t)(kbase + lm) * Nn + n0 + lk4 * 4];

    for (int k0 = 0; k0 < nk; k0 += 32) {    // all quarters: same trip count
        __syncthreads();                     // smem free
        As[qr][lk4 * 4 + 0][lm] = va.x;
        As[qr][lk4 * 4 + 1][lm] = va.y;
        As[qr][lk4 * 4 + 2][lm] = va.z;
        As[qr][lk4 * 4 + 3][lm] = va.w;
        if (TRANS_B) {
            Bs[qr][lk4 * 4 + 0][lm] = vb.x;
            Bs[qr][lk4 * 4 + 1][lm] = vb.y;
            Bs[qr][lk4 * 4 + 2][lm] = vb.z;
            Bs[qr][lk4 * 4 + 3][lm] = vb.w;
        } else {
            Bs[qr][lm][lk4 * 4 + 0] = vb.x;
            Bs[qr][lm][lk4 * 4 + 1] = vb.y;
            Bs[qr][lm][lk4 * 4 + 2] = vb.z;
            Bs[qr][lm][lk4 * 4 + 3] = vb.w;
        }
        __syncthreads();                     // tiles visible

        // Prefetch next k-block (overlaps compute)
        if (k0 + 32 < nk) {
            const int kk = kbase + k0 + 32;
            va = *(const float4*)&A[(size_t)(m0 + lm) * Kk + kk + lk4 * 4];
            if (TRANS_B) vb = *(const float4*)&Bm[(size_t)(n0 + lm) * Kk + kk + lk4 * 4];
            else         vb = *(const float4*)&Bm[(size_t)(kk + lm) * Nn + n0 + lk4 * 4];
        }

        #pragma unroll
        for (int k = 0; k < 32; k++) {
            const float2 a = *(const float2*)&As[qr][k][ty * 2];
            const float2 b = *(const float2*)&Bs[qr][k][tx * 2];
            c00 += a.x * b.x; c01 += a.x * b.y;
            c10 += a.y * b.x; c11 += a.y * b.y;
        }
    }

    // Pairwise reduction: (q2->slot0, q3->slot1) += into q0,q1; then q1->slot0 += q0.
    __syncthreads();                         // all compute done
    if (qr >= 2) {
        float (*Cr)[33] = Cred[qr - 2];
        Cr[ty * 2    ][tx * 2    ] = c00;
        Cr[ty * 2    ][tx * 2 + 1] = c01;
        Cr[ty * 2 + 1][tx * 2    ] = c10;
        Cr[ty * 2 + 1][tx * 2 + 1] = c11;
    }
    __syncthreads();
    if (qr < 2) {
        float (*Cr)[33] = Cred[qr];
        c00 += Cr[ty * 2    ][tx * 2    ];
        c01 += Cr[ty * 2    ][tx * 2 + 1];
        c10 += Cr[ty * 2 + 1][tx * 2    ];
        c11 += Cr[ty * 2 + 1][tx * 2 + 1];
    }
    __syncthreads();
    if (qr == 1) {
        float (*Cr)[33] = Cred[0];
        Cr[ty * 2    ][tx * 2    ] = c00;
        Cr[ty * 2    ][tx * 2 + 1] = c01;
        Cr[ty * 2 + 1][tx * 2    ] = c10;
        Cr[ty * 2 + 1][tx * 2 + 1] = c11;
    }
    __syncthreads();
    if (qr == 0) {
        float (*Cr)[33] = Cred[0];
        c00 += Cr[ty * 2    ][tx * 2    ];
        c01 += Cr[ty * 2    ][tx * 2 + 1];
        c10 += Cr[ty * 2 + 1][tx * 2    ];
        c11 += Cr[ty * 2 + 1][tx * 2 + 1];
        float* Cp = C + (size_t)(m0 + ty * 2) * Nn + n0 + tx * 2;
        Cp[0] = c00 * scale;  Cp[1] = c01 * scale;
        Cp[Nn] = c10 * scale; Cp[Nn + 1] = c11 * scale;
    }
    __syncthreads();                         // smem reusable by caller's next call
}

// Standalone split-K x4 gemm (for out = y @ wv)
template <int TRANS_B>
__global__ __launch_bounds__(1024) void gemm32k4(const float* __restrict__ A,
                                                 const float* __restrict__ Bm,
                                                 float* __restrict__ C,
                                                 int M, int Nn, int Kk, float scale) {
    __shared__ float As[4][32][36];
    __shared__ float Bs[4][32][36];
    __shared__ float Cred[2][32][33];
    gemm32k4_body<TRANS_B>(A, Bm, C, blockIdx.y * 32, blockIdx.x * 32,
                           Nn, Kk, scale, As, Bs, Cred);
}

// Fused Q = t@wq then qk = (Q@wk^T)*rsqrtN.  128 CTAs x 1024 thr, grid barrier.
__global__ __launch_bounds__(1024) void k_qk(const float* __restrict__ wq,
                                             const float* __restrict__ wk,
                                             float rsqrtN) {
    __shared__ float As[4][32][36];
    __shared__ float Bs[4][32][36];
    __shared__ float Cred[2][32][33];
    const int cta = blockIdx.x;              // 0..127 over 8x16 tiles
    const int m0 = (cta >> 4) * 32, n0 = (cta & 15) * 32;

    gemm32k4_body<0>(g_t, wq, g_q, m0, n0, N_, F_, 1.f, As, Bs, Cred);
    grid_sync_128();
    gemm32k4_body<1>(g_q, wk, g_qk, m0, n0, F_, N_, rsqrtN, As, Bs, Cred);
}

// ---------------------------------------------------------------------------
// Pass B: scores + online softmax + weighted accumulate. EXACT R8 structure.
// Dynamic smem: qks[512] | buf0[WT*512] | buf1[WT*512]   (67584 B)
// ---------------------------------------------------------------------------
__global__ __launch_bounds__(512, 2) void k_attn(const float* __restrict__ x) {
    extern __shared__ float sm[];
    float* qks  = sm;                  // 512
    float* bufs[2] = { sm + F_, sm + F_ + WT * F_ };
    __shared__ float sc[WT];
    __shared__ float ps[WT];

    const int b = blockIdx.x, tid = threadIdx.x;
    const int wi = tid >> 5, lane = tid & 31;

    qks[tid] = g_qk[b * F_ + tid];
    const float4* xb4 = (const float4*)(x + (size_t)b * W_ * F_);

    // Preload tile 0
    issue_tile(bufs[0], xb4, 0, tid);
    __syncthreads();                         // qks visible

    float qkr[16];
    #pragma unroll
    for (int j = 0; j < 16; j++) qkr[j] = qks[lane + 32 * j];

    float m = -1e30f, s = 0.f, y = 0.f;

    for (int t = 0; t < NT; t++) {
        const int cur = t & 1, nxt = cur ^ 1;
        if (t < NT - 1) {
            issue_tile(bufs[nxt], xb4, (t + 1) * WT, tid);
            cp_wait<1>();
        } else {
            cp_wait<0>();
        }
        __syncthreads();                     // tile cur ready (also guards sc reuse)

        // Each warp: one word's dot product (qk already carries rsqrt(N))
        float d = 0.f;
        const float* xw = &bufs[cur][wi * F_];
        #pragma unroll
        for (int j = 0; j < 16; j++) d += xw[lane + 32 * j] * qkr[j];
        #pragma unroll
        for (int o = 16; o > 0; o >>= 1) d += __shfl_xor_sync(0xffffffffu, d, o);
        if (lane == 0) sc[wi] = d;
        __syncthreads();                     // sc ready

        // mn/corr uniform across threads; p[w] computed once by 16 threads
        float mn = m;
        #pragma unroll
        for (int w = 0; w < WT; w++) mn = fmaxf(mn, sc[w]);
        const float corr = __expf(m - mn);
        if (tid < WT) ps[tid] = __expf(sc[tid] - mn);
        m = mn;
        __syncthreads();                     // ps ready

        // Accumulate (thread owns f = tid)
        float pr[WT];
        #pragma unroll
        for (int w = 0; w < WT; w++) pr[w] = ps[w];
        float psum = 0.f;
        #pragma unroll
        for (int w = 0; w < WT; w++) psum += pr[w];
        s = s * corr + psum;
        y *= corr;
        #pragma unroll
        for (int w = 0; w < WT; w++) y += pr[w] * bufs[cur][w * F_ + tid];
        // no tail barrier: cp.async arrival latency covers the next writes.
    }
    g_y[b * F_ + tid] = y / s;
}

// ---------------------------------------------------------------------------
extern "C" void kernel_launch(void* const* d_in, const int* in_sizes, int n_in,
                              void* d_out, int out_size) {
    const float* x    = (const float*)d_in[0];
    const float* wk   = (const float*)d_in[1];
    const float* wq   = (const float*)d_in[2];
    const float* wv   = (const float*)d_in[3];
    const float* wvec = (const float*)d_in[4];
    float* out = (float*)d_out;

    float* py;
    cudaGetSymbolAddress((void**)&py, g_y);

    const int pipe_smem = (F_ + 2 * WT * F_) * sizeof(float);   // 67584
    cudaFuncSetAttribute(k_t,    cudaFuncAttributeMaxDynamicSharedMemorySize, pipe_smem);
    cudaFuncSetAttribute(k_attn, cudaFuncAttributeMaxDynamicSharedMemorySize, pipe_smem);

    const float rsqrtN = 0.04419417382415922f;  // 1/sqrt(512)

    // Pass A over x: t
    k_t<<<B_, 512, pipe_smem>>>(x, wvec);
    // qk = (t @ wq @ wk^T) * rsqrtN   (fused, grid barrier inside)
    k_qk<<<NBQK, 1024>>>(wq, wk, rsqrtN);
    // Pass B over x: attention
    k_attn<<<B_, 512, pipe_smem>>>(x);
    // out = y @ wv               (256x512x512, split-K x4)
    gemm32k4<0><<<dim3(N_ / 32, B_ / 32), 1024>>>(py, wv, out, B_, N_, F_, 1.f);
}